// round 17
// baseline (speedup 1.0000x reference)
#include <cuda_runtime.h>

#define S      256
#define NB     128
#define L      256
#define NL     64
#define VOCAB  32000

typedef unsigned long long ull;

// K1 dynamic smem (R6 layout):
//   TsmU2 [16][256] ulonglong2 = 65536 B   (T tail: 2 states x 32 j per thread)
//   xs    [2][2][256] float    =  4096 B   (double-buffered state vec per chain)
//   part  [2][2][256] float    =  4096 B   (partials: [chain][half][state])
//   tok   [2][256] int         =  2048 B
#define SMEM1  (65536 + 4096 + 4096 + 2048)

// K2 dynamic smem: esm[2][128][36] + osm[2][32][64]  (double-buffered pipeline)
#define SMEM2  (2*128*36*4 + 2*32*64*4)

// scratch
__device__ float g_fwd[L * NB * S];   // fprime[t][b][s]  (pre-e-multiply forward)
__device__ float g_bwd[L * NB * S];   // b[t][b][s]

__device__ __forceinline__ void ffma2(ull &a, ull b, ull c) {
    asm("fma.rn.f32x2 %0, %1, %2, %0;" : "+l"(a) : "l"(b), "l"(c));
}
__device__ __forceinline__ float hsum2(ull lo, ull hi) {
    float2 a = *reinterpret_cast<float2*>(&lo);
    float2 b = *reinterpret_cast<float2*>(&hi);
    return (a.x + a.y) + (b.x + b.y);
}
__device__ __forceinline__ ull packdup(float e) {
    ull r;
    asm("mov.b64 %0, {%1, %1};" : "=l"(r) : "f"(e));
    return r;
}

// ---------------------------------------------------------------------------
// K1 — R6 exact (protected baseline: 287us). 128 CTAs x 256 threads,
// 2 chains/CTA. bid<64: fwd batches (2p,2p+1); bid>=64: bwd.
// Thread (h=tid>>7, u=tid&127) owns states {u, u+128}, j in [128h, 128h+128),
// T split 96 reg / 32 smem floats per state. Packed fma.rn.f32x2;
// smem partials; 2 full barriers/step; deferred output STG.
// ---------------------------------------------------------------------------
__global__ __launch_bounds__(256, 1)
void hmm_scan_kernel(const void* __restrict__ sent_raw,
                     const float* __restrict__ emb,
                     const float* __restrict__ Tm)
{
    extern __shared__ char smem_raw[];
    ulonglong2* TsmU2 = (ulonglong2*)smem_raw;              // [16][256]
    float* xs   = (float*)(smem_raw + 65536);               // [p][c][256]
    float* part = (float*)(smem_raw + 65536 + 4096);        // [c][h][256]
    int*   tok  = (int*)  (smem_raw + 65536 + 8192);        // [c][256]
    __shared__ int s_i64;

    const int  tid = threadIdx.x;
    const int  h   = tid >> 7;
    const int  u   = tid & 127;
    const int  j0  = h << 7;
    const int  bid = blockIdx.x;
    const bool bwd = (bid >= 64);
    const int  b0  = (bid & 63) * 2;
    const int  b1  = b0 + 1;

    // --- detect sentences dtype (int64 vs int32) ---
    if (tid == 0) {
        const long long* s64 = (const long long*)sent_raw;
        int f = 1;
        for (int k = 0; k < 64; k++) {
            long long v = s64[k];
            if (v < 0 || v >= VOCAB) { f = 0; break; }
        }
        s_i64 = f;
    }
    __syncthreads();

    // --- tokens for both chains ---
    if (s_i64) {
        const long long* s64 = (const long long*)sent_raw;
        tok[tid]       = (int)s64[b0 * L + tid];
        tok[256 + tid] = (int)s64[b1 * L + tid];
    } else {
        const int* s32 = (const int*)sent_raw;
        tok[tid]       = s32[b0 * L + tid];
        tok[256 + tid] = s32[b1 * L + tid];
    }

    // --- T slices: states u (A) and u+128 (B), j in [j0, j0+128):
    //     96 floats in regs (48 ull), 32 floats in smem (8 ulonglong2) each ---
    ull TrA[48], TrB[48];
    if (!bwd) {
        const float4* rowA = (const float4*)(Tm + u * S + j0);
        const float4* rowB = (const float4*)(Tm + (u + 128) * S + j0);
        #pragma unroll
        for (int g = 0; g < 24; g++) {
            ((float4*)TrA)[g] = rowA[g];
            ((float4*)TrB)[g] = rowB[g];
        }
        #pragma unroll
        for (int g = 0; g < 8; g++) {
            TsmU2[g * 256 + tid]       = ((const ulonglong2*)rowA)[24 + g];
            TsmU2[(8 + g) * 256 + tid] = ((const ulonglong2*)rowB)[24 + g];
        }
    } else {
        #pragma unroll
        for (int g = 0; g < 24; g++) {
            int j = j0 + 4 * g;
            ((float4*)TrA)[g] = make_float4(Tm[(j+0)*S + u],       Tm[(j+1)*S + u],
                                            Tm[(j+2)*S + u],       Tm[(j+3)*S + u]);
            ((float4*)TrB)[g] = make_float4(Tm[(j+0)*S + u + 128], Tm[(j+1)*S + u + 128],
                                            Tm[(j+2)*S + u + 128], Tm[(j+3)*S + u + 128]);
        }
        #pragma unroll
        for (int g = 0; g < 8; g++) {
            int j = j0 + 96 + 4 * g;
            float4 a4 = make_float4(Tm[(j+0)*S + u],       Tm[(j+1)*S + u],
                                    Tm[(j+2)*S + u],       Tm[(j+3)*S + u]);
            float4 b4 = make_float4(Tm[(j+0)*S + u + 128], Tm[(j+1)*S + u + 128],
                                    Tm[(j+2)*S + u + 128], Tm[(j+3)*S + u + 128]);
            TsmU2[g * 256 + tid]       = *reinterpret_cast<ulonglong2*>(&a4);
            TsmU2[(8 + g) * 256 + tid] = *reinterpret_cast<ulonglong2*>(&b4);
        }
    }

    float* outg = bwd ? g_bwd : g_fwd;

    // --- step 0 ---
    const int t0 = bwd ? (L - 1) : 0;
    {
        float e0 = emb[tok[t0] * S + tid];
        float e1 = emb[tok[256 + t0] * S + tid];
        if (!bwd) {
            outg[(t0 * NB + b0) * S + tid] = 1.0f;    // fprime[0] = 1
            outg[(t0 * NB + b1) * S + tid] = 1.0f;
        } else {
            outg[(t0 * NB + b0) * S + tid] = e0;      // b[L-1] = e[L-1]
            outg[(t0 * NB + b1) * S + tid] = e1;
        }
        xs[tid]       = e0;
        xs[256 + tid] = e1;
    }
    __syncthreads();

    const int dt = bwd ? -1 : 1;
    int t = t0;
    int p = 0;

    // deferred-output registers
    float o0 = 0.f, o1 = 0.f;
    int   tprev = -1;

    for (int step = 1; step < L; step++) {
        t += dt;

        // deferred output write from previous step (overlaps this matvec)
        if (tprev >= 0) {
            outg[(tprev * NB + b0) * S + tid] = o0;
            outg[(tprev * NB + b1) * S + tid] = o1;
        }

        // e prefetch: consumed only after bar1
        float en0 = emb[tok[t] * S + tid];
        float en1 = emb[tok[256 + t] * S + tid];

        const ulonglong2* X0 = (const ulonglong2*)(xs + p * 512 + j0);
        const ulonglong2* X1 = (const ulonglong2*)(xs + p * 512 + 256 + j0);

        ull a00l = 0, a00h = 0, a01l = 0, a01h = 0;   // state u:     chain0, chain1
        ull a10l = 0, a10h = 0, a11l = 0, a11h = 0;   // state u+128

        #pragma unroll
        for (int g = 0; g < 24; g++) {
            ulonglong2 x0 = X0[g];
            ulonglong2 x1 = X1[g];
            ffma2(a00l, TrA[2*g],   x0.x); ffma2(a00h, TrA[2*g+1], x0.y);
            ffma2(a01l, TrA[2*g],   x1.x); ffma2(a01h, TrA[2*g+1], x1.y);
            ffma2(a10l, TrB[2*g],   x0.x); ffma2(a10h, TrB[2*g+1], x0.y);
            ffma2(a11l, TrB[2*g],   x1.x); ffma2(a11h, TrB[2*g+1], x1.y);
        }
        #pragma unroll
        for (int g = 0; g < 8; g++) {
            ulonglong2 tA = TsmU2[g * 256 + tid];
            ulonglong2 tB = TsmU2[(8 + g) * 256 + tid];
            ulonglong2 x0 = X0[24 + g];
            ulonglong2 x1 = X1[24 + g];
            ffma2(a00l, tA.x, x0.x); ffma2(a00h, tA.y, x0.y);
            ffma2(a01l, tA.x, x1.x); ffma2(a01h, tA.y, x1.y);
            ffma2(a10l, tB.x, x0.x); ffma2(a10h, tB.y, x0.y);
            ffma2(a11l, tB.x, x1.x); ffma2(a11h, tB.y, x1.y);
        }

        // partials: part[c][h][s]
        part[h * 256 + u]             = hsum2(a00l, a00h);
        part[h * 256 + u + 128]       = hsum2(a10l, a10h);
        part[512 + h * 256 + u]       = hsum2(a01l, a01h);
        part[512 + h * 256 + u + 128] = hsum2(a11l, a11h);
        __syncthreads();

        // combine: thread tid handles state tid, both chains
        float s0 = part[tid]       + part[256 + tid];
        float s1 = part[512 + tid] + part[768 + tid];
        float nx0 = s0 * en0;
        float nx1 = s1 * en1;

        // stash outputs for deferred write (after bar2)
        o0 = bwd ? nx0 : s0;
        o1 = bwd ? nx1 : s1;
        tprev = t;

        p ^= 1;
        xs[p * 512 + tid]       = nx0;
        xs[p * 512 + 256 + tid] = nx1;
        __syncthreads();
    }

    // final deferred write
    outg[(tprev * NB + b0) * S + tid] = o0;
    outg[(tprev * NB + b1) * S + tid] = o1;
}

// ---------------------------------------------------------------------------
// K2 v5: software-pipelined. 256 CTAs, tile = 128 rows x 64 cols, 8x4 per
// thread, packed fma.rn.f32x2. s-chunks of 32, DOUBLE-BUFFERED esm/osm:
// next chunk's fv/bv/O prefetched into registers at chunk top (LDG latency
// hidden under the inner loop), FMUL+STS into the other buffer at chunk end.
// ---------------------------------------------------------------------------
__global__ __launch_bounds__(256, 2)
void hmm_proj_kernel(const float* __restrict__ Om, float* __restrict__ outp)
{
    extern __shared__ char smem2[];
    float* esm = (float*)smem2;                   // [2][128][36]
    float* osm = (float*)(smem2 + 2*128*36*4);    // [2][32][64]

    const int tid = threadIdx.x;
    const int r0  = blockIdx.x * 128;
    const int rg  = tid >> 4;
    const int cg  = tid & 15;

    // per-thread load slots (chunk = 128 rows x 32 s)
    const int rr0 = tid >> 3;            // kk*32 rows apart per kk
    const int ss0 = (tid & 7) * 4;
    const int os0 = tid >> 4;            // O rows (kk*16 apart)
    const int on0 = (tid & 15) * 4;

    ull acc01[8] = {0,0,0,0,0,0,0,0};
    ull acc23[8] = {0,0,0,0,0,0,0,0};

    // --- prologue: chunk 0 direct load ---
    #pragma unroll
    for (int kk = 0; kk < 4; kk++) {
        int rr = kk * 32 + rr0;
        float4 fv = *(const float4*)&g_fwd[(r0 + rr) * S + ss0];
        float4 bv = *(const float4*)&g_bwd[(r0 + rr) * S + ss0];
        float4 ev = make_float4(fv.x * bv.x, fv.y * bv.y, fv.z * bv.z, fv.w * bv.w);
        *(float4*)&esm[rr * 36 + ss0] = ev;
    }
    #pragma unroll
    for (int kk = 0; kk < 2; kk++) {
        int ss = kk * 16 + os0;
        *(float4*)&osm[ss * 64 + on0] = *(const float4*)&Om[ss * NL + on0];
    }
    __syncthreads();

    for (int ch = 0; ch < 8; ch++) {
        const int cur = ch & 1;
        const float* ecur = esm + cur * (128 * 36);
        const float* ocur = osm + cur * (32 * 64);

        // prefetch next chunk into registers (hidden under inner loop)
        float4 pf_f[4], pf_b[4], pf_o[2];
        if (ch < 7) {
            const int s1 = (ch + 1) * 32;
            #pragma unroll
            for (int kk = 0; kk < 4; kk++) {
                int rr = kk * 32 + rr0;
                pf_f[kk] = *(const float4*)&g_fwd[(r0 + rr) * S + s1 + ss0];
                pf_b[kk] = *(const float4*)&g_bwd[(r0 + rr) * S + s1 + ss0];
            }
            #pragma unroll
            for (int kk = 0; kk < 2; kk++) {
                int ss = kk * 16 + os0;
                pf_o[kk] = *(const float4*)&Om[(s1 + ss) * NL + on0];
            }
        }

        // inner compute on current buffer
        #pragma unroll 4
        for (int sc = 0; sc < 32; sc += 2) {
            ulonglong2 ov0 = *(const ulonglong2*)&ocur[sc * 64 + cg * 4];
            ulonglong2 ov1 = *(const ulonglong2*)&ocur[(sc + 1) * 64 + cg * 4];
            #pragma unroll
            for (int k = 0; k < 8; k++) {
                float2 ep = *(const float2*)&ecur[(rg * 8 + k) * 36 + sc];
                ull e0 = packdup(ep.x);
                ull e1 = packdup(ep.y);
                ffma2(acc01[k], e0, ov0.x);
                ffma2(acc23[k], e0, ov0.y);
                ffma2(acc01[k], e1, ov1.x);
                ffma2(acc23[k], e1, ov1.y);
            }
        }

        // stage next chunk into the other buffer
        if (ch < 7) {
            float* enx = esm + (cur ^ 1) * (128 * 36);
            float* onx = osm + (cur ^ 1) * (32 * 64);
            #pragma unroll
            for (int kk = 0; kk < 4; kk++) {
                int rr = kk * 32 + rr0;
                float4 ev = make_float4(pf_f[kk].x * pf_b[kk].x,
                                        pf_f[kk].y * pf_b[kk].y,
                                        pf_f[kk].z * pf_b[kk].z,
                                        pf_f[kk].w * pf_b[kk].w);
                *(float4*)&enx[rr * 36 + ss0] = ev;
            }
            #pragma unroll
            for (int kk = 0; kk < 2; kk++) {
                int ss = kk * 16 + os0;
                *(float4*)&onx[ss * 64 + on0] = pf_o[kk];
            }
        }
        __syncthreads();
    }

    // write: r = t*128 + b  ->  out[(b*L + t)*NL + n]
    #pragma unroll
    for (int k = 0; k < 8; k++) {
        int r  = r0 + rg * 8 + k;
        int t  = r >> 7;
        int bb = r & 127;
        float2 lo = *reinterpret_cast<float2*>(&acc01[k]);
        float2 hi = *reinterpret_cast<float2*>(&acc23[k]);
        float4 v  = make_float4(lo.x, lo.y, hi.x, hi.y);
        *(float4*)&outp[(bb * L + t) * NL + cg * 4] = v;
    }
}

extern "C" void kernel_launch(void* const* d_in, const int* in_sizes, int n_in,
                              void* d_out, int out_size)
{
    (void)in_sizes; (void)n_in; (void)out_size;
    const void*  sent = d_in[0];
    const float* emb  = (const float*)d_in[1];
    const float* Tm   = (const float*)d_in[2];
    const float* Om   = (const float*)d_in[3];
    float* outp = (float*)d_out;

    cudaFuncSetAttribute(hmm_scan_kernel,
                         cudaFuncAttributeMaxDynamicSharedMemorySize, SMEM1);
    cudaFuncSetAttribute(hmm_proj_kernel,
                         cudaFuncAttributeMaxDynamicSharedMemorySize, SMEM2);

    hmm_scan_kernel<<<128, 256, SMEM1>>>(sent, emb, Tm);
    hmm_proj_kernel<<<256, 256, SMEM2>>>(Om, outp);
}